// round 1
// baseline (speedup 1.0000x reference)
#include <cuda_runtime.h>
#include <cuda_bf16.h>

#define NN    10000
#define EMAXX 160000
#define ETOT  (EMAXX + NN)
#define FMAXD 512

// ---------------- device scratch (no allocations allowed) ----------------
__device__ int   g_is64;
__device__ int   g_deg[NN];
__device__ float g_dinv[NN];
__device__ int   g_off[NN + 1];
__device__ int   g_cur[NN];
__device__ int   g_crow[ETOT];
__device__ float g_cnorm[ETOT];
__device__ float g_bufA[(size_t)NN * FMAXD];
__device__ float g_bufB[(size_t)NN * FMAXD];

// ---------------- index dtype detection (int64 vs int32) ----------------
__global__ void k_detect(const void* ei, int E) {
    if (threadIdx.x == 0 && blockIdx.x == 0) {
        const long long* p = (const long long*)ei;
        int is64 = 1;
        int lim = (E < 128) ? E : 128;
        for (int i = 0; i < lim; i++) {
            long long v = p[i];
            if (v < 0 || v >= NN) { is64 = 0; break; }
        }
        g_is64 = is64;
    }
}

__device__ __forceinline__ int ld_idx(const void* p, long long i) {
    if (g_is64) return (int)((const long long*)p)[i];
    return ((const int*)p)[i];
}

// ---------------- graph preprocessing ----------------
__global__ void k_init() {
    int i = blockIdx.x * blockDim.x + threadIdx.x;
    if (i < NN) { g_deg[i] = 1; g_cur[i] = 0; }   // deg starts at 1 (self loop)
}

__global__ void k_deg(const void* ei, int E) {
    int e = blockIdx.x * blockDim.x + threadIdx.x;
    if (e < E) {
        int c = ld_idx(ei, (long long)E + e);
        atomicAdd(&g_deg[c], 1);
    }
}

__global__ void k_dinv() {
    int i = blockIdx.x * blockDim.x + threadIdx.x;
    if (i < NN) g_dinv[i] = rsqrtf((float)g_deg[i]);
}

// single-block exclusive scan of g_deg -> g_off
__global__ void k_scan() {
    __shared__ int s[1024];
    const int CH = 10;  // 1024*10 >= 10000
    int t = threadIdx.x;
    int base = t * CH;
    int loc[CH];
    int sum = 0;
#pragma unroll
    for (int j = 0; j < CH; j++) {
        int idx = base + j;
        int v = (idx < NN) ? g_deg[idx] : 0;
        loc[j] = sum;
        sum += v;
    }
    s[t] = sum;
    __syncthreads();
    for (int d = 1; d < 1024; d <<= 1) {
        int v = (t >= d) ? s[t - d] : 0;
        __syncthreads();
        s[t] += v;
        __syncthreads();
    }
    int excl = (t > 0) ? s[t - 1] : 0;
#pragma unroll
    for (int j = 0; j < CH; j++) {
        int idx = base + j;
        if (idx < NN) g_off[idx] = excl + loc[j];
    }
    if (t == 0) g_off[NN] = s[1023];
}

__global__ void k_fill(const void* ei, int E) {
    int e = blockIdx.x * blockDim.x + threadIdx.x;
    int tot = E + NN;
    if (e >= tot) return;
    int r, c;
    if (e < E) {
        r = ld_idx(ei, e);
        c = ld_idx(ei, (long long)E + e);
    } else {
        r = e - E;   // self loop
        c = r;
    }
    int p = atomicAdd(&g_cur[c], 1);
    int idx = g_off[c] + p;
    g_crow[idx]  = r;
    g_cnorm[idx] = g_dinv[r] * g_dinv[c];
}

// ---------------- SpMM: out[c,:] = sum_e norm_e * h[row_e,:] ----------------
// one block per node, FD/4 threads, float4 per thread
template <int FD>
__global__ void k_spmm(const float* __restrict__ h, float* __restrict__ out) {
    const int V = FD / 4;
    int node = blockIdx.x;
    int tid  = threadIdx.x;
    int s = g_off[node];
    int e = g_off[node + 1];
    const float4* h4 = (const float4*)h;
    float4 acc = make_float4(0.f, 0.f, 0.f, 0.f);
    int i = s;
    for (; i + 4 <= e; i += 4) {
        int   r0 = g_crow[i],     r1 = g_crow[i + 1];
        int   r2 = g_crow[i + 2], r3 = g_crow[i + 3];
        float w0 = g_cnorm[i],     w1 = g_cnorm[i + 1];
        float w2 = g_cnorm[i + 2], w3 = g_cnorm[i + 3];
        float4 v0 = h4[(size_t)r0 * V + tid];
        float4 v1 = h4[(size_t)r1 * V + tid];
        float4 v2 = h4[(size_t)r2 * V + tid];
        float4 v3 = h4[(size_t)r3 * V + tid];
        acc.x += w0 * v0.x; acc.y += w0 * v0.y; acc.z += w0 * v0.z; acc.w += w0 * v0.w;
        acc.x += w1 * v1.x; acc.y += w1 * v1.y; acc.z += w1 * v1.z; acc.w += w1 * v1.w;
        acc.x += w2 * v2.x; acc.y += w2 * v2.y; acc.z += w2 * v2.z; acc.w += w2 * v2.w;
        acc.x += w3 * v3.x; acc.y += w3 * v3.y; acc.z += w3 * v3.z; acc.w += w3 * v3.w;
    }
    for (; i < e; i++) {
        int   r = g_crow[i];
        float w = g_cnorm[i];
        float4 v = h4[(size_t)r * V + tid];
        acc.x += w * v.x; acc.y += w * v.y; acc.z += w * v.z; acc.w += w * v.w;
    }
    ((float4*)out)[(size_t)node * V + tid] = acc;
}

// ---------------- GEMM: C = A[M,K] @ B[K,512] + bias, optional relu --------
__global__ __launch_bounds__(256, 2)
void k_gemm(const float* __restrict__ A, const float* __restrict__ B,
            const float* __restrict__ bias, float* __restrict__ C,
            int M, int K, int relu) {
    const int BM = 128, BN = 128, BK = 8, TM = 8, TN = 8;
    const int N = 512;
    __shared__ float As[BK][BM];
    __shared__ float Bs[BK][BN];

    int bx = blockIdx.x;            // N tiles (4)
    int by = blockIdx.y;            // M tiles (79)
    int tid = threadIdx.x;
    int trow = tid / 16, tcol = tid % 16;

    int aRow = tid / 2;             // 128 rows
    int aCol = (tid % 2) * 4;       // 2 x float4 per row
    int bRow = tid / 32;            // 8 rows
    int bCol = (tid % 32) * 4;      // 32 x float4 per row

    float acc[TM][TN];
#pragma unroll
    for (int i = 0; i < TM; i++)
#pragma unroll
        for (int j = 0; j < TN; j++) acc[i][j] = 0.f;

    int rowBase = by * BM;

    for (int k0 = 0; k0 < K; k0 += BK) {
        int gr = rowBase + aRow;
        float4 av = make_float4(0.f, 0.f, 0.f, 0.f);
        if (gr < M) av = *(const float4*)&A[(size_t)gr * K + k0 + aCol];
        As[aCol + 0][aRow] = av.x;
        As[aCol + 1][aRow] = av.y;
        As[aCol + 2][aRow] = av.z;
        As[aCol + 3][aRow] = av.w;
        float4 bv = *(const float4*)&B[(size_t)(k0 + bRow) * N + bx * BN + bCol];
        *(float4*)&Bs[bRow][bCol] = bv;
        __syncthreads();

#pragma unroll
        for (int k = 0; k < BK; k++) {
            float4 a0 = *(const float4*)&As[k][trow * TM];
            float4 a1 = *(const float4*)&As[k][trow * TM + 4];
            float4 b0 = *(const float4*)&Bs[k][tcol * TN];
            float4 b1 = *(const float4*)&Bs[k][tcol * TN + 4];
            float ar[TM] = {a0.x, a0.y, a0.z, a0.w, a1.x, a1.y, a1.z, a1.w};
            float br[TN] = {b0.x, b0.y, b0.z, b0.w, b1.x, b1.y, b1.z, b1.w};
#pragma unroll
            for (int i = 0; i < TM; i++)
#pragma unroll
                for (int j = 0; j < TN; j++)
                    acc[i][j] += ar[i] * br[j];
        }
        __syncthreads();
    }

#pragma unroll
    for (int i = 0; i < TM; i++) {
        int gr = rowBase + trow * TM + i;
        if (gr >= M) continue;
#pragma unroll
        for (int j = 0; j < TN; j += 4) {
            int gc = bx * BN + tcol * TN + j;
            float4 v;
            v.x = acc[i][j + 0] + bias[gc + 0];
            v.y = acc[i][j + 1] + bias[gc + 1];
            v.z = acc[i][j + 2] + bias[gc + 2];
            v.w = acc[i][j + 3] + bias[gc + 3];
            if (relu) {
                v.x = fmaxf(v.x, 0.f); v.y = fmaxf(v.y, 0.f);
                v.z = fmaxf(v.z, 0.f); v.w = fmaxf(v.w, 0.f);
            }
            *(float4*)&C[(size_t)gr * 512 + gc] = v;
        }
    }
}

// ---------------- launch ----------------
extern "C" void kernel_launch(void* const* d_in, const int* in_sizes, int n_in,
                              void* d_out, int out_size) {
    const float* x  = (const float*)d_in[0];
    const void*  ei = d_in[1];
    const float* W1 = (const float*)d_in[2];
    const float* b1 = (const float*)d_in[3];
    const float* W2 = (const float*)d_in[4];
    const float* b2 = (const float*)d_in[5];
    const float* W3 = (const float*)d_in[6];
    const float* b3 = (const float*)d_in[7];
    const float* W4 = (const float*)d_in[8];
    const float* b4 = (const float*)d_in[9];
    float* out = (float*)d_out;

    int E = in_sizes[1] / 2;

    float *bufA, *bufB;
    cudaGetSymbolAddress((void**)&bufA, g_bufA);
    cudaGetSymbolAddress((void**)&bufB, g_bufB);

    // ---- preprocessing ----
    k_detect<<<1, 32>>>(ei, E);
    k_init<<<(NN + 127) / 128, 128>>>();
    k_deg<<<(E + 255) / 256, 256>>>(ei, E);
    k_dinv<<<(NN + 127) / 128, 128>>>();
    k_scan<<<1, 1024>>>();
    k_fill<<<(E + NN + 255) / 256, 256>>>(ei, E);

    dim3 ggrid(4, (NN + 127) / 128);

    // ---- layer 1: spmm (256-wide) then gemm K=256 ----
    k_spmm<256><<<NN, 64>>>(x, bufA);
    k_gemm<<<ggrid, 256>>>(bufA, W1, b1, bufB, NN, 256, 1);

    // ---- layer 2 ----
    k_spmm<512><<<NN, 128>>>(bufB, bufA);
    k_gemm<<<ggrid, 256>>>(bufA, W2, b2, bufB, NN, 512, 1);

    // ---- layer 3 ----
    k_spmm<512><<<NN, 128>>>(bufB, bufA);
    k_gemm<<<ggrid, 256>>>(bufA, W3, b3, bufB, NN, 512, 1);

    // ---- layer 4 (no relu, write d_out) ----
    k_spmm<512><<<NN, 128>>>(bufB, bufA);
    k_gemm<<<ggrid, 256>>>(bufA, W4, b4, out, NN, 512, 0);
}

// round 3
// speedup vs baseline: 1.9691x; 1.9691x over previous
#include <cuda_runtime.h>
#include <cuda_bf16.h>
#include <cstdint>

#define NN    10000
#define EMAXX 160000
#define ETOT  (EMAXX + NN)

// ---------------- device scratch (no allocations allowed) ----------------
__device__ int   g_is64;
__device__ int   g_deg[NN];
__device__ float g_dinv[NN];
__device__ int   g_off[NN + 1];
__device__ int   g_cur[NN];
__device__ int   g_crow[ETOT];
__device__ float g_cnorm[ETOT];
__device__ float g_h[(size_t)NN * 512];               // fp32 activations (GEMM out)
__device__ __nv_bfloat16 g_ah[(size_t)NN * 512];      // A hi (SpMM out)
__device__ __nv_bfloat16 g_al[(size_t)NN * 512];      // A lo
__device__ __nv_bfloat16 g_wh[4 * 512 * 512];         // W^T hi, [N=512 rows][K cols]
__device__ __nv_bfloat16 g_wl[4 * 512 * 512];         // W^T lo

// ---------------- index dtype detection ----------------
__global__ void k_detect(const void* ei, int E) {
    if (threadIdx.x == 0 && blockIdx.x == 0) {
        const long long* p = (const long long*)ei;
        int is64 = 1;
        int lim = (E < 128) ? E : 128;
        for (int i = 0; i < lim; i++) {
            long long v = p[i];
            if (v < 0 || v >= NN) { is64 = 0; break; }
        }
        g_is64 = is64;
    }
}
__device__ __forceinline__ int ld_idx(const void* p, long long i) {
    if (g_is64) return (int)((const long long*)p)[i];
    return ((const int*)p)[i];
}

// ---------------- graph preprocessing ----------------
__global__ void k_init() {
    int i = blockIdx.x * blockDim.x + threadIdx.x;
    if (i < NN) { g_deg[i] = 1; g_cur[i] = 0; }
}
__global__ void k_deg(const void* ei, int E) {
    int e = blockIdx.x * blockDim.x + threadIdx.x;
    if (e < E) atomicAdd(&g_deg[ld_idx(ei, (long long)E + e)], 1);
}
__global__ void k_dinv() {
    int i = blockIdx.x * blockDim.x + threadIdx.x;
    if (i < NN) g_dinv[i] = rsqrtf((float)g_deg[i]);
}
__global__ void k_scan() {
    __shared__ int s[1024];
    const int CH = 10;
    int t = threadIdx.x;
    int base = t * CH, loc[CH], sum = 0;
#pragma unroll
    for (int j = 0; j < CH; j++) {
        int idx = base + j;
        int v = (idx < NN) ? g_deg[idx] : 0;
        loc[j] = sum; sum += v;
    }
    s[t] = sum;
    __syncthreads();
    for (int d = 1; d < 1024; d <<= 1) {
        int v = (t >= d) ? s[t - d] : 0;
        __syncthreads();
        s[t] += v;
        __syncthreads();
    }
    int excl = (t > 0) ? s[t - 1] : 0;
#pragma unroll
    for (int j = 0; j < CH; j++) {
        int idx = base + j;
        if (idx < NN) g_off[idx] = excl + loc[j];
    }
    if (t == 0) g_off[NN] = s[1023];
}
__global__ void k_fill(const void* ei, int E) {
    int e = blockIdx.x * blockDim.x + threadIdx.x;
    int tot = E + NN;
    if (e >= tot) return;
    int r, c;
    if (e < E) { r = ld_idx(ei, e); c = ld_idx(ei, (long long)E + e); }
    else { r = e - E; c = r; }
    int p = atomicAdd(&g_cur[c], 1);
    int idx = g_off[c] + p;
    g_crow[idx]  = r;
    g_cnorm[idx] = g_dinv[r] * g_dinv[c];
}

// W [K,512] fp32 -> Wt hi/lo [512 rows(N)][K cols] bf16 (tiled transpose)
__global__ void k_wconv(const float* __restrict__ W, __nv_bfloat16* __restrict__ wh,
                        __nv_bfloat16* __restrict__ wl, int K) {
    __shared__ float t[32][33];
    int k0 = blockIdx.x * 32, n0 = blockIdx.y * 32;
    int tx = threadIdx.x, ty = threadIdx.y;
    t[ty][tx] = W[(size_t)(k0 + ty) * 512 + n0 + tx];
    __syncthreads();
    float v = t[tx][ty];                               // = W[k0+tx][n0+ty]
    __nv_bfloat16 h = __float2bfloat16(v);
    float lo = v - __bfloat162float(h);
    size_t o = (size_t)(n0 + ty) * K + k0 + tx;
    wh[o] = h;
    wl[o] = __float2bfloat16(lo);
}

// ---------------- SpMM: acc fp32, write bf16 hi/lo split ----------------
__device__ __forceinline__ uint32_t pack2(float a, float b) {
    __nv_bfloat162 t = __floats2bfloat162_rn(a, b);
    return *(uint32_t*)&t;
}
template <int FD>
__global__ void k_spmm_split(const float* __restrict__ h,
                             __nv_bfloat16* __restrict__ ah,
                             __nv_bfloat16* __restrict__ al) {
    const int V = FD / 4;
    int node = blockIdx.x;
    int tid  = threadIdx.x;
    int s = g_off[node], e = g_off[node + 1];
    const float4* h4 = (const float4*)h;
    float4 acc = make_float4(0.f, 0.f, 0.f, 0.f);
    int i = s;
    for (; i + 4 <= e; i += 4) {
        int   r0 = g_crow[i],     r1 = g_crow[i + 1];
        int   r2 = g_crow[i + 2], r3 = g_crow[i + 3];
        float w0 = g_cnorm[i],     w1 = g_cnorm[i + 1];
        float w2 = g_cnorm[i + 2], w3 = g_cnorm[i + 3];
        float4 v0 = h4[(size_t)r0 * V + tid];
        float4 v1 = h4[(size_t)r1 * V + tid];
        float4 v2 = h4[(size_t)r2 * V + tid];
        float4 v3 = h4[(size_t)r3 * V + tid];
        acc.x += w0 * v0.x; acc.y += w0 * v0.y; acc.z += w0 * v0.z; acc.w += w0 * v0.w;
        acc.x += w1 * v1.x; acc.y += w1 * v1.y; acc.z += w1 * v1.z; acc.w += w1 * v1.w;
        acc.x += w2 * v2.x; acc.y += w2 * v2.y; acc.z += w2 * v2.z; acc.w += w2 * v2.w;
        acc.x += w3 * v3.x; acc.y += w3 * v3.y; acc.z += w3 * v3.z; acc.w += w3 * v3.w;
    }
    for (; i < e; i++) {
        int   r = g_crow[i];
        float w = g_cnorm[i];
        float4 v = h4[(size_t)r * V + tid];
        acc.x += w * v.x; acc.y += w * v.y; acc.z += w * v.z; acc.w += w * v.w;
    }
    float hx = __bfloat162float(__float2bfloat16(acc.x));
    float hy = __bfloat162float(__float2bfloat16(acc.y));
    float hz = __bfloat162float(__float2bfloat16(acc.z));
    float hw = __bfloat162float(__float2bfloat16(acc.w));
    uint2 uh, ul;
    uh.x = pack2(acc.x, acc.y); uh.y = pack2(acc.z, acc.w);
    ul.x = pack2(acc.x - hx, acc.y - hy); ul.y = pack2(acc.z - hz, acc.w - hw);
    size_t base = (size_t)node * FD + tid * 4;
    *(uint2*)(ah + base) = uh;
    *(uint2*)(al + base) = ul;
}

// ---------------- HMMA helpers ----------------
__device__ __forceinline__ uint32_t smem_u32(const void* p) {
    uint32_t a;
    asm("{ .reg .u64 t; cvta.to.shared.u64 t, %1; cvt.u32.u64 %0, t; }" : "=r"(a) : "l"(p));
    return a;
}
#define LDSM_X4(r0, r1, r2, r3, addr) \
    asm volatile("ldmatrix.sync.aligned.m8n8.x4.shared.b16 {%0,%1,%2,%3}, [%4];" \
        : "=r"(r0), "=r"(r1), "=r"(r2), "=r"(r3) : "r"(addr))
#define MMA16816(d, a0, a1, a2, a3, b0, b1) \
    asm volatile("mma.sync.aligned.m16n8k16.row.col.f32.bf16.bf16.f32 " \
        "{%0,%1,%2,%3}, {%4,%5,%6,%7}, {%8,%9}, {%0,%1,%2,%3};" \
        : "+f"((d)[0]), "+f"((d)[1]), "+f"((d)[2]), "+f"((d)[3]) \
        : "r"(a0), "r"(a1), "r"(a2), "r"(a3), "r"(b0), "r"(b1))
#define CP_ASYNC16(dst, src, sz) \
    asm volatile("cp.async.cg.shared.global [%0], [%1], 16, %2;" \
        :: "r"(dst), "l"(src), "r"(sz) : "memory")
#define CP_COMMIT() asm volatile("cp.async.commit_group;" ::: "memory")
#define CP_WAIT(n)  asm volatile("cp.async.wait_group %0;" :: "n"(n) : "memory")

// ---------------- bf16-split HMMA GEMM --------------------------------------
// C[M,512] = A[M,K] @ Wt^T + bias (relu opt); A,Wt in hi/lo bf16, K-major.
// CTA tile 128x128x32, 8 warps (warp tile 32x64), cp.async double buffer.
#define SP 40   // padded smem row stride (bf16 elems): bank-conflict-free
template <int K>
__global__ void __launch_bounds__(256, 1)
k_gemm_mma(const __nv_bfloat16* __restrict__ Ah, const __nv_bfloat16* __restrict__ Al,
           const __nv_bfloat16* __restrict__ Wh, const __nv_bfloat16* __restrict__ Wl,
           const float* __restrict__ bias, float* __restrict__ C, int relu) {
    extern __shared__ __nv_bfloat16 sm[];
    const int M = NN;
    const int NC = K / 32;
    const int TILE = 128 * SP;                   // elems per tile
    const int STAGE = 4 * TILE;                  // Ah, Al, Bh, Bl

    int tid = threadIdx.x;
    int wid = tid >> 5, lane = tid & 31;
    int wm = wid & 3, wn = wid >> 2;             // warp grid 4 x 2
    int bx = blockIdx.x, by = blockIdx.y;

    float acc[2][8][4];
#pragma unroll
    for (int i = 0; i < 2; i++)
#pragma unroll
        for (int j = 0; j < 8; j++)
#pragma unroll
            for (int q = 0; q < 4; q++) acc[i][j][q] = 0.f;

    // global load mapping: 2 chunks/thread/tile; chunk = 8 bf16 = 16B
    int ldrow0 = tid >> 1;                       // rows 0..127 (idx/4 for it0)
    // idx = it*256 + tid; row = idx>>2, kc = idx&3
    auto stage_load = [&](int st, int k0) {
        const __nv_bfloat16* srcs[4] = {Ah, Al, Wh, Wl};
        __nv_bfloat16* dst = sm + st * STAGE;
#pragma unroll
        for (int t = 0; t < 4; t++) {
            const __nv_bfloat16* src = srcs[t];
            bool isA = (t < 2);
            int rowBase = isA ? by * 128 : bx * 128;
#pragma unroll
            for (int it = 0; it < 2; it++) {
                int idx = it * 256 + tid;
                int r = idx >> 2, kc = idx & 3;
                int gr = rowBase + r;
                uint32_t d = smem_u32(dst + t * TILE + r * SP + kc * 8);
                const __nv_bfloat16* s = src + (size_t)gr * K + k0 + kc * 8;
                int sz = (!isA || gr < M) ? 16 : 0;
                CP_ASYNC16(d, s, sz);
            }
        }
    };

    stage_load(0, 0);
    CP_COMMIT();

    for (int i = 0; i < NC; i++) {
        if (i + 1 < NC) { stage_load((i + 1) & 1, (i + 1) * 32); CP_COMMIT(); }
        if (i + 1 < NC) CP_WAIT(1); else CP_WAIT(0);
        __syncthreads();

        __nv_bfloat16* st = sm + (i & 1) * STAGE;
        uint32_t sAh = smem_u32(st);
        uint32_t sAl = smem_u32(st + TILE);
        uint32_t sBh = smem_u32(st + 2 * TILE);
        uint32_t sBl = smem_u32(st + 3 * TILE);

#pragma unroll
        for (int ks = 0; ks < 2; ks++) {
            int arow = wm * 32 + (lane & 15);
            int koff = ks * 16 + (lane >> 4) * 8;
            uint32_t ah[2][4], al[2][4], bh[4][4], bl[4][4];
#pragma unroll
            for (int mi = 0; mi < 2; mi++) {
                uint32_t ad = (uint32_t)(((arow + mi * 16) * SP + koff) * 2);
                LDSM_X4(ah[mi][0], ah[mi][1], ah[mi][2], ah[mi][3], sAh + ad);
                LDSM_X4(al[mi][0], al[mi][1], al[mi][2], al[mi][3], sAl + ad);
            }
            int brow = wn * 64 + (lane & 15);
#pragma unroll
            for (int ni = 0; ni < 4; ni++) {
                uint32_t bd = (uint32_t)(((brow + ni * 16) * SP + koff) * 2);
                LDSM_X4(bh[ni][0], bh[ni][1], bh[ni][2], bh[ni][3], sBh + bd);
                LDSM_X4(bl[ni][0], bl[ni][1], bl[ni][2], bl[ni][3], sBl + bd);
            }
#pragma unroll
            for (int mi = 0; mi < 2; mi++)
#pragma unroll
                for (int ni = 0; ni < 4; ni++) {
                    // n8 tile even: {b0,b2}; odd: {b1,b3}
                    MMA16816(acc[mi][ni * 2 + 0], ah[mi][0], ah[mi][1], ah[mi][2], ah[mi][3],
                             bh[ni][0], bh[ni][2]);
                    MMA16816(acc[mi][ni * 2 + 1], ah[mi][0], ah[mi][1], ah[mi][2], ah[mi][3],
                             bh[ni][1], bh[ni][3]);
                    MMA16816(acc[mi][ni * 2 + 0], ah[mi][0], ah[mi][1], ah[mi][2], ah[mi][3],
                             bl[ni][0], bl[ni][2]);
                    MMA16816(acc[mi][ni * 2 + 1], ah[mi][0], ah[mi][1], ah[mi][2], ah[mi][3],
                             bl[ni][1], bl[ni][3]);
                    MMA16816(acc[mi][ni * 2 + 0], al[mi][0], al[mi][1], al[mi][2], al[mi][3],
                             bh[ni][0], bh[ni][2]);
                    MMA16816(acc[mi][ni * 2 + 1], al[mi][0], al[mi][1], al[mi][2], al[mi][3],
                             bh[ni][1], bh[ni][3]);
                }
        }
        __syncthreads();
    }

    // epilogue
#pragma unroll
    for (int mi = 0; mi < 2; mi++) {
        int grow = by * 128 + wm * 32 + mi * 16 + (lane >> 2);
#pragma unroll
        for (int ni = 0; ni < 8; ni++) {
            int gcol = bx * 128 + wn * 64 + ni * 8 + (lane & 3) * 2;
            float bx0 = bias[gcol], bx1 = bias[gcol + 1];
            float2 v0, v1;
            v0.x = acc[mi][ni][0] + bx0; v0.y = acc[mi][ni][1] + bx1;
            v1.x = acc[mi][ni][2] + bx0; v1.y = acc[mi][ni][3] + bx1;
            if (relu) {
                v0.x = fmaxf(v0.x, 0.f); v0.y = fmaxf(v0.y, 0.f);
                v1.x = fmaxf(v1.x, 0.f); v1.y = fmaxf(v1.y, 0.f);
            }
            if (grow < M)     *(float2*)(C + (size_t)grow * 512 + gcol) = v0;
            if (grow + 8 < M) *(float2*)(C + (size_t)(grow + 8) * 512 + gcol) = v1;
        }
    }
}

// ---------------- launch ----------------
extern "C" void kernel_launch(void* const* d_in, const int* in_sizes, int n_in,
                              void* d_out, int out_size) {
    const float* x  = (const float*)d_in[0];
    const void*  ei = d_in[1];
    const float* W1 = (const float*)d_in[2];
    const float* b1 = (const float*)d_in[3];
    const float* W2 = (const float*)d_in[4];
    const float* b2 = (const float*)d_in[5];
    const float* W3 = (const float*)d_in[6];
    const float* b3 = (const float*)d_in[7];
    const float* W4 = (const float*)d_in[8];
    const float* b4 = (const float*)d_in[9];
    float* out = (float*)d_out;

    int E = in_sizes[1] / 2;

    float *h;
    __nv_bfloat16 *ah, *al, *wh, *wl;
    cudaGetSymbolAddress((void**)&h,  g_h);
    cudaGetSymbolAddress((void**)&ah, g_ah);
    cudaGetSymbolAddress((void**)&al, g_al);
    cudaGetSymbolAddress((void**)&wh, g_wh);
    cudaGetSymbolAddress((void**)&wl, g_wl);

    const int GSMEM = 2 * 4 * 128 * SP * 2;   // 2 stages * 4 tiles * 128*SP bf16
    static int attr_done = 0;
    if (!attr_done) {
        cudaFuncSetAttribute(k_gemm_mma<256>, cudaFuncAttributeMaxDynamicSharedMemorySize, GSMEM);
        cudaFuncSetAttribute(k_gemm_mma<512>, cudaFuncAttributeMaxDynamicSharedMemorySize, GSMEM);
        attr_done = 1;
    }

    // ---- preprocessing ----
    k_detect<<<1, 32>>>(ei, E);
    k_init<<<(NN + 127) / 128, 128>>>();
    k_deg<<<(E + 255) / 256, 256>>>(ei, E);
    k_dinv<<<(NN + 127) / 128, 128>>>();
    k_scan<<<1, 1024>>>();
    k_fill<<<(E + NN + 255) / 256, 256>>>(ei, E);

    dim3 tb(32, 32);
    k_wconv<<<dim3(8, 16),  tb>>>(W1, wh + 0 * 512 * 512, wl + 0 * 512 * 512, 256);
    k_wconv<<<dim3(16, 16), tb>>>(W2, wh + 1 * 512 * 512, wl + 1 * 512 * 512, 512);
    k_wconv<<<dim3(16, 16), tb>>>(W3, wh + 2 * 512 * 512, wl + 2 * 512 * 512, 512);
    k_wconv<<<dim3(16, 16), tb>>>(W4, wh + 3 * 512 * 512, wl + 3 * 512 * 512, 512);

    dim3 ggrid(4, (NN + 127) / 128);

    // ---- layer 1 (K=256) ----
    k_spmm_split<256><<<NN, 64>>>(x, ah, al);
    k_gemm_mma<256><<<ggrid, 256, GSMEM>>>(ah, al, wh + 0 * 512 * 512, wl + 0 * 512 * 512, b1, h, 1);
    // ---- layer 2 ----
    k_spmm_split<512><<<NN, 128>>>(h, ah, al);
    k_gemm_mma<512><<<ggrid, 256, GSMEM>>>(ah, al, wh + 1 * 512 * 512, wl + 1 * 512 * 512, b2, h, 1);
    // ---- layer 3 ----
    k_spmm_split<512><<<NN, 128>>>(h, ah, al);
    k_gemm_mma<512><<<ggrid, 256, GSMEM>>>(ah, al, wh + 2 * 512 * 512, wl + 2 * 512 * 512, b3, h, 1);
    // ---- layer 4 (no relu, to d_out) ----
    k_spmm_split<512><<<NN, 128>>>(h, ah, al);
    k_gemm_mma<512><<<ggrid, 256, GSMEM>>>(ah, al, wh + 3 * 512 * 512, wl + 3 * 512 * 512, b4, out, 0);
}

// round 4
// speedup vs baseline: 2.1061x; 1.0696x over previous
#include <cuda_runtime.h>
#include <cuda_bf16.h>
#include <cstdint>

#define NN    10000
#define EMAXX 160000
#define ETOT  (EMAXX + NN)

// ---------------- device scratch (no allocations allowed) ----------------
__device__ int   g_is64;
__device__ int   g_deg[NN];
__device__ float g_dinv[NN];
__device__ int   g_off[NN + 1];
__device__ int   g_cur[NN];
__device__ int   g_crow[ETOT];
__device__ float g_cnorm[ETOT];
__device__ float g_h[(size_t)NN * 512];               // fp32 activations (GEMM out)
__device__ __nv_bfloat16 g_ah[(size_t)NN * 512];      // A hi (SpMM out)
__device__ __nv_bfloat16 g_al[(size_t)NN * 512];      // A lo
__device__ __nv_bfloat16 g_wh[4 * 512 * 512];         // W^T hi, [N rows][K cols]
__device__ __nv_bfloat16 g_wl[4 * 512 * 512];         // W^T lo

__device__ __forceinline__ int ld_idx(const void* p, long long i) {
    if (g_is64) return (int)((const long long*)p)[i];
    return ((const int*)p)[i];
}

// ---------------- preprocessing (fused) ----------------
// init deg/cur + warp-parallel dtype detect (block 0, warp 0)
__global__ void k_init(const void* ei, int E) {
    int i = blockIdx.x * blockDim.x + threadIdx.x;
    if (i < NN) { g_deg[i] = 1; g_cur[i] = 0; }
    if (blockIdx.x == 0 && threadIdx.x < 32) {
        const long long* p = (const long long*)ei;
        int lim = (E < 64) ? E : 64;
        int bad = 0;
        for (int j = threadIdx.x; j < lim; j += 32) {
            long long v = p[j];
            bad |= (v < 0 || v >= NN);
        }
        unsigned m = __ballot_sync(0xFFFFFFFFu, bad);
        if (threadIdx.x == 0) g_is64 = (m == 0);
    }
}
__global__ void k_deg(const void* ei, int E) {
    int e = blockIdx.x * blockDim.x + threadIdx.x;
    if (e < E) atomicAdd(&g_deg[ld_idx(ei, (long long)E + e)], 1);
}
// single-block scan of deg -> off, plus dinv
__global__ void k_scan() {
    __shared__ int s[1024];
    const int CH = 10;
    int t = threadIdx.x;
    int base = t * CH, loc[CH], sum = 0;
#pragma unroll
    for (int j = 0; j < CH; j++) {
        int idx = base + j;
        int v = (idx < NN) ? g_deg[idx] : 0;
        if (idx < NN) g_dinv[idx] = rsqrtf((float)v);
        loc[j] = sum; sum += v;
    }
    s[t] = sum;
    __syncthreads();
    for (int d = 1; d < 1024; d <<= 1) {
        int v = (t >= d) ? s[t - d] : 0;
        __syncthreads();
        s[t] += v;
        __syncthreads();
    }
    int excl = (t > 0) ? s[t - 1] : 0;
#pragma unroll
    for (int j = 0; j < CH; j++) {
        int idx = base + j;
        if (idx < NN) g_off[idx] = excl + loc[j];
    }
    if (t == 0) g_off[NN] = s[1023];
}
__global__ void k_fill(const void* ei, int E) {
    int e = blockIdx.x * blockDim.x + threadIdx.x;
    int tot = E + NN;
    if (e >= tot) return;
    int r, c;
    if (e < E) { r = ld_idx(ei, e); c = ld_idx(ei, (long long)E + e); }
    else { r = e - E; c = r; }
    int p = atomicAdd(&g_cur[c], 1);
    int idx = g_off[c] + p;
    g_crow[idx]  = r;
    g_cnorm[idx] = g_dinv[r] * g_dinv[c];
}

// all 4 weights: W [K,512] fp32 -> Wt hi/lo [512][K] bf16 (tiled transpose)
__global__ void k_wconv_all(const float* __restrict__ W1, const float* __restrict__ W2,
                            const float* __restrict__ W3, const float* __restrict__ W4,
                            __nv_bfloat16* __restrict__ whB, __nv_bfloat16* __restrict__ wlB) {
    __shared__ float t[32][33];
    int l = blockIdx.z;
    const float* W = (l == 0) ? W1 : (l == 1) ? W2 : (l == 2) ? W3 : W4;
    int K = (l == 0) ? 256 : 512;
    int k0 = blockIdx.x * 32, n0 = blockIdx.y * 32;
    if (k0 >= K) return;
    __nv_bfloat16* wh = whB + (size_t)l * 512 * 512;
    __nv_bfloat16* wl = wlB + (size_t)l * 512 * 512;
    int tx = threadIdx.x, ty = threadIdx.y;
    t[ty][tx] = W[(size_t)(k0 + ty) * 512 + n0 + tx];
    __syncthreads();
    float v = t[tx][ty];                               // = W[k0+tx][n0+ty]
    __nv_bfloat16 h = __float2bfloat16(v);
    float lo = v - __bfloat162float(h);
    size_t o = (size_t)(n0 + ty) * K + k0 + tx;
    wh[o] = h;
    wl[o] = __float2bfloat16(lo);
}

// ---------------- SpMM: acc fp32, write bf16 hi/lo split ----------------
__device__ __forceinline__ uint32_t pack2(float a, float b) {
    __nv_bfloat162 t = __floats2bfloat162_rn(a, b);
    return *(uint32_t*)&t;
}
template <int FD>
__global__ void k_spmm_split(const float* __restrict__ h,
                             __nv_bfloat16* __restrict__ ah,
                             __nv_bfloat16* __restrict__ al) {
    const int V = FD / 4;
    int node = blockIdx.x;
    int tid  = threadIdx.x;
    int s = g_off[node], e = g_off[node + 1];
    const float4* h4 = (const float4*)h;
    float4 acc = make_float4(0.f, 0.f, 0.f, 0.f);
    int i = s;
    for (; i + 4 <= e; i += 4) {
        int   r0 = g_crow[i],     r1 = g_crow[i + 1];
        int   r2 = g_crow[i + 2], r3 = g_crow[i + 3];
        float w0 = g_cnorm[i],     w1 = g_cnorm[i + 1];
        float w2 = g_cnorm[i + 2], w3 = g_cnorm[i + 3];
        float4 v0 = h4[(size_t)r0 * V + tid];
        float4 v1 = h4[(size_t)r1 * V + tid];
        float4 v2 = h4[(size_t)r2 * V + tid];
        float4 v3 = h4[(size_t)r3 * V + tid];
        acc.x += w0 * v0.x; acc.y += w0 * v0.y; acc.z += w0 * v0.z; acc.w += w0 * v0.w;
        acc.x += w1 * v1.x; acc.y += w1 * v1.y; acc.z += w1 * v1.z; acc.w += w1 * v1.w;
        acc.x += w2 * v2.x; acc.y += w2 * v2.y; acc.z += w2 * v2.z; acc.w += w2 * v2.w;
        acc.x += w3 * v3.x; acc.y += w3 * v3.y; acc.z += w3 * v3.z; acc.w += w3 * v3.w;
    }
    for (; i < e; i++) {
        int   r = g_crow[i];
        float w = g_cnorm[i];
        float4 v = h4[(size_t)r * V + tid];
        acc.x += w * v.x; acc.y += w * v.y; acc.z += w * v.z; acc.w += w * v.w;
    }
    float hx = __bfloat162float(__float2bfloat16(acc.x));
    float hy = __bfloat162float(__float2bfloat16(acc.y));
    float hz = __bfloat162float(__float2bfloat16(acc.z));
    float hw = __bfloat162float(__float2bfloat16(acc.w));
    uint2 uh, ul;
    uh.x = pack2(acc.x, acc.y); uh.y = pack2(acc.z, acc.w);
    ul.x = pack2(acc.x - hx, acc.y - hy); ul.y = pack2(acc.z - hz, acc.w - hw);
    size_t base = (size_t)node * FD + tid * 4;
    *(uint2*)(ah + base) = uh;
    *(uint2*)(al + base) = ul;
}

// ---------------- HMMA helpers ----------------
__device__ __forceinline__ uint32_t smem_u32(const void* p) {
    uint32_t a;
    asm("{ .reg .u64 t; cvta.to.shared.u64 t, %1; cvt.u32.u64 %0, t; }" : "=r"(a) : "l"(p));
    return a;
}
#define LDSM_X4(r0, r1, r2, r3, addr) \
    asm volatile("ldmatrix.sync.aligned.m8n8.x4.shared.b16 {%0,%1,%2,%3}, [%4];" \
        : "=r"(r0), "=r"(r1), "=r"(r2), "=r"(r3) : "r"(addr))
#define MMA16816(d, a0, a1, a2, a3, b0, b1) \
    asm volatile("mma.sync.aligned.m16n8k16.row.col.f32.bf16.bf16.f32 " \
        "{%0,%1,%2,%3}, {%4,%5,%6,%7}, {%8,%9}, {%0,%1,%2,%3};" \
        : "+f"((d)[0]), "+f"((d)[1]), "+f"((d)[2]), "+f"((d)[3]) \
        : "r"(a0), "r"(a1), "r"(a2), "r"(a3), "r"(b0), "r"(b1))
#define CP_ASYNC16(dst, src, sz) \
    asm volatile("cp.async.cg.shared.global [%0], [%1], 16, %2;" \
        :: "r"(dst), "l"(src), "r"(sz) : "memory")
#define CP_COMMIT() asm volatile("cp.async.commit_group;" ::: "memory")
#define CP_WAIT(n)  asm volatile("cp.async.wait_group %0;" :: "n"(n) : "memory")

// ---------------- bf16-split HMMA GEMM --------------------------------------
// C[M,512] = A[M,K] @ Wt^T + bias (relu opt); A,Wt in hi/lo bf16, K-major.
// CTA tile 128x128x32, 8 warps (warp tile 32x64), cp.async double buffer.
// 2 CTAs/SM: smem 80KB/CTA, <=128 regs/thread.
#define SP 40   // padded smem row stride (bf16 elems): conflict-free for ldmatrix
template <int K>
__global__ void __launch_bounds__(256, 2)
k_gemm_mma(const __nv_bfloat16* __restrict__ Ah, const __nv_bfloat16* __restrict__ Al,
           const __nv_bfloat16* __restrict__ Wh, const __nv_bfloat16* __restrict__ Wl,
           const float* __restrict__ bias, float* __restrict__ C, int relu) {
    extern __shared__ __nv_bfloat16 sm[];
    const int M = NN;
    const int NC = K / 32;
    const int TILE = 128 * SP;
    const int STAGE = 4 * TILE;

    int tid = threadIdx.x;
    int wid = tid >> 5, lane = tid & 31;
    int wm = wid & 3, wn = wid >> 2;             // warp grid 4 x 2
    int bx = blockIdx.x, by = blockIdx.y;

    float acc[2][8][4];
#pragma unroll
    for (int i = 0; i < 2; i++)
#pragma unroll
        for (int j = 0; j < 8; j++)
#pragma unroll
            for (int q = 0; q < 4; q++) acc[i][j][q] = 0.f;

    auto stage_load = [&](int st, int k0) {
        const __nv_bfloat16* srcs[4] = {Ah, Al, Wh, Wl};
        __nv_bfloat16* dst = sm + st * STAGE;
#pragma unroll
        for (int t = 0; t < 4; t++) {
            const __nv_bfloat16* src = srcs[t];
            bool isA = (t < 2);
            int rowBase = isA ? by * 128 : bx * 128;
#pragma unroll
            for (int it = 0; it < 2; it++) {
                int idx = it * 256 + tid;
                int r = idx >> 2, kc = idx & 3;
                int gr = rowBase + r;
                uint32_t d = smem_u32(dst + t * TILE + r * SP + kc * 8);
                const __nv_bfloat16* s = src + (size_t)gr * K + k0 + kc * 8;
                int sz = (!isA || gr < M) ? 16 : 0;
                CP_ASYNC16(d, s, sz);
            }
        }
    };

    stage_load(0, 0);
    CP_COMMIT();

    for (int i = 0; i < NC; i++) {
        if (i + 1 < NC) { stage_load((i + 1) & 1, (i + 1) * 32); CP_COMMIT(); }
        if (i + 1 < NC) CP_WAIT(1); else CP_WAIT(0);
        __syncthreads();

        __nv_bfloat16* st = sm + (i & 1) * STAGE;
        uint32_t sAh = smem_u32(st);
        uint32_t sAl = smem_u32(st + TILE);
        uint32_t sBh = smem_u32(st + 2 * TILE);
        uint32_t sBl = smem_u32(st + 3 * TILE);

#pragma unroll
        for (int ks = 0; ks < 2; ks++) {
            int arow = wm * 32 + (lane & 15);
            int koff = ks * 16 + (lane >> 4) * 8;
            uint32_t ah[2][4], al[2][4], bh[4][4], bl[4][4];
#pragma unroll
            for (int mi = 0; mi < 2; mi++) {
                uint32_t ad = (uint32_t)(((arow + mi * 16) * SP + koff) * 2);
                LDSM_X4(ah[mi][0], ah[mi][1], ah[mi][2], ah[mi][3], sAh + ad);
                LDSM_X4(al[mi][0], al[mi][1], al[mi][2], al[mi][3], sAl + ad);
            }
            int brow = wn * 64 + (lane & 15);
#pragma unroll
            for (int ni = 0; ni < 4; ni++) {
                uint32_t bd = (uint32_t)(((brow + ni * 16) * SP + koff) * 2);
                LDSM_X4(bh[ni][0], bh[ni][1], bh[ni][2], bh[ni][3], sBh + bd);
                LDSM_X4(bl[ni][0], bl[ni][1], bl[ni][2], bl[ni][3], sBl + bd);
            }
#pragma unroll
            for (int mi = 0; mi < 2; mi++)
#pragma unroll
                for (int ni = 0; ni < 4; ni++) {
                    MMA16816(acc[mi][ni * 2 + 0], ah[mi][0], ah[mi][1], ah[mi][2], ah[mi][3],
                             bh[ni][0], bh[ni][2]);
                    MMA16816(acc[mi][ni * 2 + 1], ah[mi][0], ah[mi][1], ah[mi][2], ah[mi][3],
                             bh[ni][1], bh[ni][3]);
                    MMA16816(acc[mi][ni * 2 + 0], ah[mi][0], ah[mi][1], ah[mi][2], ah[mi][3],
                             bl[ni][0], bl[ni][2]);
                    MMA16816(acc[mi][ni * 2 + 1], ah[mi][0], ah[mi][1], ah[mi][2], ah[mi][3],
                             bl[ni][1], bl[ni][3]);
                    MMA16816(acc[mi][ni * 2 + 0], al[mi][0], al[mi][1], al[mi][2], al[mi][3],
                             bh[ni][0], bh[ni][2]);
                    MMA16816(acc[mi][ni * 2 + 1], al[mi][0], al[mi][1], al[mi][2], al[mi][3],
                             bh[ni][1], bh[ni][3]);
                }
        }
        __syncthreads();
    }

    // epilogue
#pragma unroll
    for (int mi = 0; mi < 2; mi++) {
        int grow = by * 128 + wm * 32 + mi * 16 + (lane >> 2);
#pragma unroll
        for (int ni = 0; ni < 8; ni++) {
            int gcol = bx * 128 + wn * 64 + ni * 8 + (lane & 3) * 2;
            float bx0 = bias[gcol], bx1 = bias[gcol + 1];
            float2 v0, v1;
            v0.x = acc[mi][ni][0] + bx0; v0.y = acc[mi][ni][1] + bx1;
            v1.x = acc[mi][ni][2] + bx0; v1.y = acc[mi][ni][3] + bx1;
            if (relu) {
                v0.x = fmaxf(v0.x, 0.f); v0.y = fmaxf(v0.y, 0.f);
                v1.x = fmaxf(v1.x, 0.f); v1.y = fmaxf(v1.y, 0.f);
            }
            if (grow < M)     *(float2*)(C + (size_t)grow * 512 + gcol) = v0;
            if (grow + 8 < M) *(float2*)(C + (size_t)(grow + 8) * 512 + gcol) = v1;
        }
    }
}

// ---------------- launch ----------------
extern "C" void kernel_launch(void* const* d_in, const int* in_sizes, int n_in,
                              void* d_out, int out_size) {
    const float* x  = (const float*)d_in[0];
    const void*  ei = d_in[1];
    const float* W1 = (const float*)d_in[2];
    const float* b1 = (const float*)d_in[3];
    const float* W2 = (const float*)d_in[4];
    const float* b2 = (const float*)d_in[5];
    const float* W3 = (const float*)d_in[6];
    const float* b3 = (const float*)d_in[7];
    const float* W4 = (const float*)d_in[8];
    const float* b4 = (const float*)d_in[9];
    float* out = (float*)d_out;

    int E = in_sizes[1] / 2;

    float *h;
    __nv_bfloat16 *ah, *al, *wh, *wl;
    cudaGetSymbolAddress((void**)&h,  g_h);
    cudaGetSymbolAddress((void**)&ah, g_ah);
    cudaGetSymbolAddress((void**)&al, g_al);
    cudaGetSymbolAddress((void**)&wh, g_wh);
    cudaGetSymbolAddress((void**)&wl, g_wl);

    const int GSMEM = 2 * 4 * 128 * SP * 2;   // 2 stages * 4 tiles * 128*SP bf16 = 80KB
    static int attr_done = 0;
    if (!attr_done) {
        cudaFuncSetAttribute(k_gemm_mma<256>, cudaFuncAttributeMaxDynamicSharedMemorySize, GSMEM);
        cudaFuncSetAttribute(k_gemm_mma<512>, cudaFuncAttributeMaxDynamicSharedMemorySize, GSMEM);
        attr_done = 1;
    }

    // ---- preprocessing (4 launches + 1 weight-convert) ----
    k_init<<<(NN + 127) / 128, 128>>>(ei, E);
    k_deg<<<(E + 255) / 256, 256>>>(ei, E);
    k_scan<<<1, 1024>>>();
    k_fill<<<(E + NN + 255) / 256, 256>>>(ei, E);
    k_wconv_all<<<dim3(16, 16, 4), dim3(32, 32)>>>(W1, W2, W3, W4, wh, wl);

    dim3 ggrid(4, (NN + 127) / 128);

    // ---- layer 1 (K=256) ----
    k_spmm_split<256><<<NN, 64>>>(x, ah, al);
    k_gemm_mma<256><<<ggrid, 256, GSMEM>>>(ah, al, wh + 0 * 512 * 512, wl + 0 * 512 * 512, b1, h, 1);
    // ---- layer 2 ----
    k_spmm_split<512><<<NN, 128>>>(h, ah, al);
    k_gemm_mma<512><<<ggrid, 256, GSMEM>>>(ah, al, wh + 1 * 512 * 512, wl + 1 * 512 * 512, b2, h, 1);
    // ---- layer 3 ----
    k_spmm_split<512><<<NN, 128>>>(h, ah, al);
    k_gemm_mma<512><<<ggrid, 256, GSMEM>>>(ah, al, wh + 2 * 512 * 512, wl + 2 * 512 * 512, b3, h, 1);
    // ---- layer 4 (no relu, to d_out) ----
    k_spmm_split<512><<<NN, 128>>>(h, ah, al);
    k_gemm_mma<512><<<ggrid, 256, GSMEM>>>(ah, al, wh + 3 * 512 * 512, wl + 3 * 512 * 512, b4, out, 0);
}